// round 2
// baseline (speedup 1.0000x reference)
#include <cuda_runtime.h>
#include <cuda_bf16.h>
#include <math.h>

// ----------------------------------------------------------------------------
// OctreeRender (TensoRF-style tri-plane volume renderer)
// Inputs (metadata order):
//  0: rays          float[4096*6]
//  1: density_plane float[3*16*256*256]
//  2: density_line  float[3*16*256]
//  3: app_plane     float[3*24*256*256]
//  4: app_line      float[3*24*256]
//  5: basis_mat     float[72*3]
//  6: aabb          float[2*3]
//  7: N_samples     int (fixed = 256)
// Output: float[4096*3] rgb_map followed by float[4096] depth_map (16384 total)
// ----------------------------------------------------------------------------

#define N_RAYS    4096
#define RES       256
#define NS        256   // samples per ray
#define DC        16    // density channels
#define AC        24    // app channels

// Channel-last scratch (static __device__ — no allocation).
__device__ float g_dp[3 * RES * RES * DC];   // [i][y][x][16]
__device__ float g_ap[3 * RES * RES * AC];   // [i][y][x][24]
__device__ float g_dl[3 * RES * DC];         // [i][p][16]
__device__ float g_al[3 * RES * AC];         // [i][p][24]

// ---------------- transpose kernels: [i][c][y][x] -> [i][y][x][c] ------------

__global__ void transpose_dplane(const float* __restrict__ src) {
    // grid (8, 256, 3), block (32, 16)
    __shared__ float tile[DC][33];
    const int x = blockIdx.x * 32 + threadIdx.x;
    const int y = blockIdx.y;
    const int i = blockIdx.z;
    tile[threadIdx.y][threadIdx.x] =
        __ldg(&src[(((i * DC + threadIdx.y) * RES) + y) * RES + x]);
    __syncthreads();
    const int t = threadIdx.y * 32 + threadIdx.x;   // 0..511
    if (t < 128) {
        const int pos = t >> 2;     // x within tile
        const int q   = t & 3;      // channel quartet
        float4 v = make_float4(tile[q * 4 + 0][pos], tile[q * 4 + 1][pos],
                               tile[q * 4 + 2][pos], tile[q * 4 + 3][pos]);
        ((float4*)g_dp)[(((i * RES + y) * RES) + blockIdx.x * 32 + pos) * 4 + q] = v;
    }
}

__global__ void transpose_aplane(const float* __restrict__ src) {
    // grid (8, 256, 3), block (32, 24)
    __shared__ float tile[AC][33];
    const int x = blockIdx.x * 32 + threadIdx.x;
    const int y = blockIdx.y;
    const int i = blockIdx.z;
    tile[threadIdx.y][threadIdx.x] =
        __ldg(&src[(((i * AC + threadIdx.y) * RES) + y) * RES + x]);
    __syncthreads();
    const int t = threadIdx.y * 32 + threadIdx.x;   // 0..767
    if (t < 192) {
        const int pos = t / 6;
        const int q   = t - pos * 6;
        float4 v = make_float4(tile[q * 4 + 0][pos], tile[q * 4 + 1][pos],
                               tile[q * 4 + 2][pos], tile[q * 4 + 3][pos]);
        ((float4*)g_ap)[(((i * RES + y) * RES) + blockIdx.x * 32 + pos) * 6 + q] = v;
    }
}

__global__ void transpose_lines(const float* __restrict__ dl,
                                const float* __restrict__ al) {
    const int tid = blockIdx.x * blockDim.x + threadIdx.x;
    if (tid < 3 * DC * RES) {                 // 12288
        const int i = tid / (DC * RES);
        const int r = tid - i * (DC * RES);
        const int c = r / RES;
        const int p = r - c * RES;
        g_dl[(i * RES + p) * DC + c] = __ldg(&dl[tid]);
    }
    if (tid < 3 * AC * RES) {                 // 18432
        const int i = tid / (AC * RES);
        const int r = tid - i * (AC * RES);
        const int c = r / RES;
        const int p = r - c * RES;
        g_al[(i * RES + p) * AC + c] = __ldg(&al[tid]);
    }
}

// ---------------- render ----------------------------------------------------

__device__ __forceinline__ float bil(float v00, float v01, float v10, float v11,
                                     float wx, float wy) {
    float top = v00 * (1.0f - wx) + v01 * wx;
    float bot = v10 * (1.0f - wx) + v11 * wx;
    return top * (1.0f - wy) + bot * wy;
}

__device__ __forceinline__ void grid_coord(float u, float& w, int& i0) {
    float f  = (u + 1.0f) * 0.5f * 255.0f;
    float f0 = fminf(fmaxf(floorf(f), 0.0f), 254.0f);
    i0 = (int)f0;
    w  = f - f0;
}

__device__ __forceinline__ void samp_density(int i, float u, float v, float w,
                                             float& sig) {
    int x0, y0, p0; float wx, wy, wl;
    grid_coord(u, wx, x0);
    grid_coord(v, wy, y0);
    grid_coord(w, wl, p0);
    const float4* b  = ((const float4*)g_dp) + (((i * RES + y0) * RES) + x0) * 4;
    const float4* lb = ((const float4*)g_dl) + (i * RES + p0) * 4;
#pragma unroll
    for (int q = 0; q < 4; q++) {
        float4 v00 = b[q],        v01 = b[4 + q];
        float4 v10 = b[1024 + q], v11 = b[1028 + q];
        float4 l0  = lb[q],       l1  = lb[4 + q];
        sig += bil(v00.x, v01.x, v10.x, v11.x, wx, wy) * (l0.x * (1.0f - wl) + l1.x * wl);
        sig += bil(v00.y, v01.y, v10.y, v11.y, wx, wy) * (l0.y * (1.0f - wl) + l1.y * wl);
        sig += bil(v00.z, v01.z, v10.z, v11.z, wx, wy) * (l0.z * (1.0f - wl) + l1.z * wl);
        sig += bil(v00.w, v01.w, v10.w, v11.w, wx, wy) * (l0.w * (1.0f - wl) + l1.w * wl);
    }
}

__device__ __forceinline__ void samp_app(int i, float u, float v, float w,
                                         const float* __restrict__ s_basis,
                                         float& r0, float& r1, float& r2) {
    int x0, y0, p0; float wx, wy, wl;
    grid_coord(u, wx, x0);
    grid_coord(v, wy, y0);
    grid_coord(w, wl, p0);
    const float4* b  = ((const float4*)g_ap) + (((i * RES + y0) * RES) + x0) * 6;
    const float4* lb = ((const float4*)g_al) + (i * RES + p0) * 6;
#pragma unroll
    for (int q = 0; q < 6; q++) {
        float4 v00 = b[q],        v01 = b[6 + q];
        float4 v10 = b[1536 + q], v11 = b[1542 + q];
        float4 l0  = lb[q],       l1  = lb[6 + q];
        const int cb = (i * AC + q * 4) * 3;
        float f;
        f = bil(v00.x, v01.x, v10.x, v11.x, wx, wy) * (l0.x * (1.0f - wl) + l1.x * wl);
        r0 += f * s_basis[cb + 0]; r1 += f * s_basis[cb + 1]; r2 += f * s_basis[cb + 2];
        f = bil(v00.y, v01.y, v10.y, v11.y, wx, wy) * (l0.y * (1.0f - wl) + l1.y * wl);
        r0 += f * s_basis[cb + 3]; r1 += f * s_basis[cb + 4]; r2 += f * s_basis[cb + 5];
        f = bil(v00.z, v01.z, v10.z, v11.z, wx, wy) * (l0.z * (1.0f - wl) + l1.z * wl);
        r0 += f * s_basis[cb + 6]; r1 += f * s_basis[cb + 7]; r2 += f * s_basis[cb + 8];
        f = bil(v00.w, v01.w, v10.w, v11.w, wx, wy) * (l0.w * (1.0f - wl) + l1.w * wl);
        r0 += f * s_basis[cb + 9]; r1 += f * s_basis[cb + 10]; r2 += f * s_basis[cb + 11];
    }
}

__global__ __launch_bounds__(NS) void render_kernel(
    const float* __restrict__ rays,
    const float* __restrict__ basis,
    const float* __restrict__ aabb,
    float* __restrict__ out) {
    __shared__ float s_basis[72 * 3];
    __shared__ float s_warp[8];
    __shared__ float s_red[8][5];

    const int ray = blockIdx.x;
    const int j   = threadIdx.x;

    if (j < 216) s_basis[j] = __ldg(&basis[j]);

    // ray setup (every thread redundantly — cheap)
    float o[3], d[3], a0[3], a1[3];
#pragma unroll
    for (int k = 0; k < 3; k++) {
        o[k]  = __ldg(&rays[ray * 6 + k]);
        d[k]  = __ldg(&rays[ray * 6 + 3 + k]);
        a0[k] = __ldg(&aabb[k]);
        a1[k] = __ldg(&aabb[3 + k]);
    }
    float t_min = -1e30f, t_max = 1e30f;
#pragma unroll
    for (int k = 0; k < 3; k++) {
        float vk = (fabsf(d[k]) < 1e-6f) ? 1e-6f : d[k];
        float ra = (a1[k] - o[k]) / vk;
        float rb = (a0[k] - o[k]) / vk;
        t_min = fmaxf(t_min, fminf(ra, rb));
        t_max = fminf(t_max, fmaxf(ra, rb));
    }
    t_min = fmaxf(t_min, 0.05f);
    t_max = fmaxf(t_max, t_min + 0.001f);

    const float s  = (float)j / 255.0f;
    const float z  = t_min * (1.0f - s) + t_max * s;
    const int   ja = (j < 255) ? j : 254;
    const float sA = (float)ja / 255.0f;
    const float sB = (float)(ja + 1) / 255.0f;
    const float dist = (t_min * (1.0f - sB) + t_max * sB)
                     - (t_min * (1.0f - sA) + t_max * sA);

    float c[3];
#pragma unroll
    for (int k = 0; k < 3; k++) {
        float p = o[k] + d[k] * z;
        c[k] = (p - a0[k]) / (a1[k] - a0[k]) * 2.0f - 1.0f;
    }
    const bool inside = fabsf(c[0]) <= 1.0f && fabsf(c[1]) <= 1.0f && fabsf(c[2]) <= 1.0f;

    __syncthreads();   // s_basis ready

    float sig = 0.0f, r0 = 0.0f, r1 = 0.0f, r2 = 0.0f;
    if (inside) {
        // MAT_MODE=[(0,1),(0,2),(1,2)], VEC_MODE=[2,1,0]
        samp_density(0, c[0], c[1], c[2], sig);
        samp_density(1, c[0], c[2], c[1], sig);
        samp_density(2, c[1], c[2], c[0], sig);
        samp_app(0, c[0], c[1], c[2], s_basis, r0, r1, r2);
        samp_app(1, c[0], c[2], c[1], s_basis, r0, r1, r2);
        samp_app(2, c[1], c[2], c[0], s_basis, r0, r1, r2);
    }

    // softplus (stable) * inside, then alpha
    float sp = fmaxf(sig, 0.0f) + log1pf(expf(-fabsf(sig)));
    float alpha = inside ? (1.0f - expf(-sp * dist)) : 0.0f;
    float g = 1.0f - alpha + 1e-10f;

    // exclusive prefix product across 256 threads
    const unsigned lane = j & 31u;
    const unsigned wid  = j >> 5;
    float p = g;
#pragma unroll
    for (int off = 1; off < 32; off <<= 1) {
        float n = __shfl_up_sync(0xffffffffu, p, off);
        if (lane >= off) p *= n;
    }
    if (lane == 31) s_warp[wid] = p;
    __syncthreads();
    float woff = 1.0f;
    for (unsigned w = 0; w < wid; w++) woff *= s_warp[w];
    float pexcl = __shfl_up_sync(0xffffffffu, p, 1);
    if (lane == 0) pexcl = 1.0f;
    const float T = woff * pexcl;
    const float weight = alpha * T;

    // per-sample contributions
    float cr0 = weight * (1.0f / (1.0f + expf(-r0)));
    float cr1 = weight * (1.0f / (1.0f + expf(-r1)));
    float cr2 = weight * (1.0f / (1.0f + expf(-r2)));
    float cz  = weight * z;
    float cw  = weight;

    // block reduction of 5 values
    float vals[5] = {cr0, cr1, cr2, cz, cw};
#pragma unroll
    for (int k = 0; k < 5; k++) {
#pragma unroll
        for (int off = 16; off > 0; off >>= 1)
            vals[k] += __shfl_xor_sync(0xffffffffu, vals[k], off);
    }
    if (lane == 0) {
#pragma unroll
        for (int k = 0; k < 5; k++) s_red[wid][k] = vals[k];
    }
    __syncthreads();
    if (j == 0) {
        float sum[5] = {0, 0, 0, 0, 0};
#pragma unroll
        for (int w = 0; w < 8; w++)
#pragma unroll
            for (int k = 0; k < 5; k++) sum[k] += s_red[w][k];
        const float acc = sum[4];
        const float bg  = 1.0f - acc;   // WHITE_BG
        out[ray * 3 + 0] = fminf(fmaxf(sum[0] + bg, 0.0f), 1.0f);
        out[ray * 3 + 1] = fminf(fmaxf(sum[1] + bg, 0.0f), 1.0f);
        out[ray * 3 + 2] = fminf(fmaxf(sum[2] + bg, 0.0f), 1.0f);
        out[N_RAYS * 3 + ray] = sum[3];   // depth
    }
}

// ---------------- launch -----------------------------------------------------

extern "C" void kernel_launch(void* const* d_in, const int* in_sizes, int n_in,
                              void* d_out, int out_size) {
    const float* rays  = (const float*)d_in[0];
    const float* dp    = (const float*)d_in[1];
    const float* dl    = (const float*)d_in[2];
    const float* ap    = (const float*)d_in[3];
    const float* al    = (const float*)d_in[4];
    const float* basis = (const float*)d_in[5];
    const float* aabb  = (const float*)d_in[6];
    (void)in_sizes; (void)n_in; (void)out_size;

    transpose_dplane<<<dim3(8, 256, 3), dim3(32, 16)>>>(dp);
    transpose_aplane<<<dim3(8, 256, 3), dim3(32, 24)>>>(ap);
    transpose_lines<<<72, 256>>>(dl, al);
    render_kernel<<<N_RAYS, NS>>>(rays, basis, aabb, (float*)d_out);
}

// round 3
// speedup vs baseline: 1.6010x; 1.6010x over previous
#include <cuda_runtime.h>
#include <cuda_fp16.h>
#include <math.h>

// ----------------------------------------------------------------------------
// OctreeRender (TensoRF-style tri-plane volume renderer) — warp-cooperative
// Inputs (metadata order):
//  0: rays          float[4096*6]
//  1: density_plane float[3*16*256*256]
//  2: density_line  float[3*16*256]
//  3: app_plane     float[3*24*256*256]
//  4: app_line      float[3*24*256]
//  5: basis_mat     float[72*3]
//  6: aabb          float[2*3]
//  7: N_samples     int (fixed = 256)
// Output: float[4096*3] rgb_map then float[4096] depth_map
// ----------------------------------------------------------------------------

#define N_RAYS    4096
#define RES       256
#define NS        256
#define DC        16    // density channels (fp32, channel-last)
#define ACP       32    // app channels padded 24 -> 32 (fp16, channel-last)

// Channel-last scratch (__device__ globals: zero-initialized once; padded
// channels are never written and stay 0).
__device__ float  g_dp[3 * RES * RES * DC];    // [i][y][x][16] fp32
__device__ float  g_dl[3 * RES * DC];          // [i][p][16]   fp32
__device__ __half g_aph[3 * RES * RES * ACP];  // [i][y][x][32] fp16 (pad 0)
__device__ __half g_alh[3 * RES * ACP];        // [i][p][32]   fp16 (pad 0)

// ---------------- transpose kernels ------------------------------------------

__global__ void transpose_dplane(const float* __restrict__ src) {
    // grid (8, 256, 3), block (32, 16)
    __shared__ float tile[DC][33];
    const int x = blockIdx.x * 32 + threadIdx.x;
    const int y = blockIdx.y;
    const int i = blockIdx.z;
    tile[threadIdx.y][threadIdx.x] =
        __ldg(&src[(((i * DC + threadIdx.y) * RES) + y) * RES + x]);
    __syncthreads();
    const int t = threadIdx.y * 32 + threadIdx.x;   // 0..511
    if (t < 128) {
        const int pos = t >> 2;
        const int q   = t & 3;
        float4 v = make_float4(tile[q * 4 + 0][pos], tile[q * 4 + 1][pos],
                               tile[q * 4 + 2][pos], tile[q * 4 + 3][pos]);
        ((float4*)g_dp)[(((i * RES + y) * RES) + blockIdx.x * 32 + pos) * 4 + q] = v;
    }
}

__global__ void transpose_aplane(const float* __restrict__ src) {
    // grid (8, 256, 3), block (32, 24): [i][c][y][x] -> half [i][y][x][32]
    __shared__ float tile[24][33];
    const int x = blockIdx.x * 32 + threadIdx.x;
    const int y = blockIdx.y;
    const int i = blockIdx.z;
    tile[threadIdx.y][threadIdx.x] =
        __ldg(&src[(((i * 24 + threadIdx.y) * RES) + y) * RES + x]);
    __syncthreads();
    const int t = threadIdx.y * 32 + threadIdx.x;   // 0..767
    if (t < 384) {                                  // 32 pos * 12 half2 (c<24)
        const int pos = t / 12;
        const int hp  = t - pos * 12;               // half2 index (c = 2hp, 2hp+1)
        __half2 v = __floats2half2_rn(tile[hp * 2][pos], tile[hp * 2 + 1][pos]);
        ((__half2*)g_aph)[(((i * RES + y) * RES) + blockIdx.x * 32 + pos) * 16 + hp] = v;
    }
}

__global__ void transpose_lines(const float* __restrict__ dl,
                                const float* __restrict__ al) {
    const int tid = blockIdx.x * blockDim.x + threadIdx.x;
    if (tid < 3 * DC * RES) {                 // 12288
        const int i = tid / (DC * RES);
        const int r = tid - i * (DC * RES);
        const int c = r / RES;
        const int p = r - c * RES;
        g_dl[(i * RES + p) * DC + c] = __ldg(&dl[tid]);
    }
    if (tid < 3 * RES * ACP) {                // 24576
        const int i = tid / (RES * ACP);
        const int r = tid - i * (RES * ACP);
        const int p = r / ACP;
        const int c = r - p * ACP;
        float v = (c < 24) ? __ldg(&al[((i * 24 + c) * RES) + p]) : 0.0f;
        g_alh[(i * RES + p) * ACP + c] = __float2half(v);
    }
}

// ---------------- render -----------------------------------------------------

__device__ __forceinline__ void grid_coord(float u, float& w, int& i0) {
    float f  = (u + 1.0f) * 0.5f * 255.0f;
    float f0 = fminf(fmaxf(floorf(f), 0.0f), 254.0f);
    i0 = (int)f0;
    w  = f - f0;
}

// One plane, one sample, cooperative across 8 lanes (sub = lane&7).
// Lane holds: dxl = sub>>2 (x0 or x0+1 / p0 or p0+1), q = sub&3 (channel quartet).
__device__ __forceinline__ void gather_plane(
    int i, float u, float v, float w, int sub, int dxl, int q,
    const float* __restrict__ s_basis,
    float& sig, float& r0, float& r1, float& r2)
{
    int x0, y0, p0; float wx, wy, wl;
    grid_coord(u, wx, x0);
    grid_coord(v, wy, y0);
    grid_coord(w, wl, p0);
    const float wsel  = dxl ? wx : (1.0f - wx);
    const float lsel  = dxl ? wl : (1.0f - wl);
    const float lsel2 = 1.0f - lsel;
    const float iwy   = 1.0f - wy;

    // ---- density (fp32, 16ch): row-pair = 8 float4 ----
    {
        const float4* db = ((const float4*)g_dp) + (((i * RES + y0) * RES) + x0) * 4;
        float4 A = db[sub];
        float4 B = db[1024 + sub];
        float4 L = ((const float4*)g_dl)[(i * RES + p0) * 4 + sub];
        float4 Lp;
        Lp.x = __shfl_xor_sync(0xffffffffu, L.x, 4);
        Lp.y = __shfl_xor_sync(0xffffffffu, L.y, 4);
        Lp.z = __shfl_xor_sync(0xffffffffu, L.z, 4);
        Lp.w = __shfl_xor_sync(0xffffffffu, L.w, 4);
        float mx = (A.x * iwy + B.x * wy) * wsel;
        float my = (A.y * iwy + B.y * wy) * wsel;
        float mz = (A.z * iwy + B.z * wy) * wsel;
        float mw = (A.w * iwy + B.w * wy) * wsel;
        float lx = L.x * lsel + Lp.x * lsel2;
        float ly = L.y * lsel + Lp.y * lsel2;
        float lz = L.z * lsel + Lp.z * lsel2;
        float lw = L.w * lsel + Lp.w * lsel2;
        sig += mx * lx + my * ly + mz * lz + mw * lw;
    }

    // ---- app (fp16 pad32): row-pair = 8 uint4 (8 halves each) ----
    {
        const uint4* ab = ((const uint4*)g_aph) + (((i * RES + y0) * RES) + x0) * 4;
        uint4 ua = ab[sub];
        uint4 ub = ab[1024 + sub];
        uint4 ul = ((const uint4*)g_alh)[(i * RES + p0) * 4 + sub];
        uint4 up;
        up.x = __shfl_xor_sync(0xffffffffu, ul.x, 4);
        up.y = __shfl_xor_sync(0xffffffffu, ul.y, 4);
        up.z = __shfl_xor_sync(0xffffffffu, ul.z, 4);
        up.w = __shfl_xor_sync(0xffffffffu, ul.w, 4);
        const __half2* pa  = (const __half2*)&ua;
        const __half2* pb  = (const __half2*)&ub;
        const __half2* pl  = (const __half2*)&ul;
        const __half2* plp = (const __half2*)&up;
        const int cb = (i * ACP + q * 8) * 3;
#pragma unroll
        for (int hh = 0; hh < 4; hh++) {
            float2 a  = __half22float2(pa[hh]);
            float2 b  = __half22float2(pb[hh]);
            float2 l  = __half22float2(pl[hh]);
            float2 lp = __half22float2(plp[hh]);
            float m0  = (a.x * iwy + b.x * wy) * wsel;
            float m1  = (a.y * iwy + b.y * wy) * wsel;
            float l0  = l.x * lsel + lp.x * lsel2;
            float l1  = l.y * lsel + lp.y * lsel2;
            float f0  = m0 * l0;
            float f1  = m1 * l1;
            const int c0 = cb + hh * 6;
            r0 += f0 * s_basis[c0 + 0];
            r1 += f0 * s_basis[c0 + 1];
            r2 += f0 * s_basis[c0 + 2];
            r0 += f1 * s_basis[c0 + 3];
            r1 += f1 * s_basis[c0 + 4];
            r2 += f1 * s_basis[c0 + 5];
        }
    }
}

__global__ __launch_bounds__(NS, 3) void render_kernel(
    const float* __restrict__ rays,
    const float* __restrict__ basis,
    const float* __restrict__ aabb,
    float* __restrict__ out) {
    __shared__ float s_basis[3 * ACP * 3];   // padded 96 channels x 3
    __shared__ float s_sig[NS];
    __shared__ float s_r0[NS], s_r1[NS], s_r2[NS];
    __shared__ float s_warp[8];
    __shared__ float s_red[8][5];

    const int ray  = blockIdx.x;
    const int tid  = threadIdx.x;
    const int lane = tid & 31;
    const int wid  = tid >> 5;
    const int g    = lane >> 3;   // 4 groups per warp
    const int sub  = lane & 7;    // lane within group
    const int dxl  = sub >> 2;
    const int q    = sub & 3;

    // load padded basis: cpad in [0,96), s_basis[cpad*3+k]
    for (int idx = tid; idx < 3 * ACP * 3; idx += NS) {
        const int cpad = idx / 3;
        const int k    = idx - cpad * 3;
        const int i    = cpad >> 5;
        const int cc   = cpad & 31;
        s_basis[idx] = (cc < 24) ? __ldg(&basis[(i * 24 + cc) * 3 + k]) : 0.0f;
    }

    // ray setup (every thread)
    float o[3], d[3], a0[3], a1[3];
#pragma unroll
    for (int k = 0; k < 3; k++) {
        o[k]  = __ldg(&rays[ray * 6 + k]);
        d[k]  = __ldg(&rays[ray * 6 + 3 + k]);
        a0[k] = __ldg(&aabb[k]);
        a1[k] = __ldg(&aabb[3 + k]);
    }
    float t_min = -1e30f, t_max = 1e30f;
#pragma unroll
    for (int k = 0; k < 3; k++) {
        float vk = (fabsf(d[k]) < 1e-6f) ? 1e-6f : d[k];
        float ra = (a1[k] - o[k]) / vk;
        float rb = (a0[k] - o[k]) / vk;
        t_min = fmaxf(t_min, fminf(ra, rb));
        t_max = fminf(t_max, fmaxf(ra, rb));
    }
    t_min = fmaxf(t_min, 0.05f);
    t_max = fmaxf(t_max, t_min + 0.001f);

    __syncthreads();   // s_basis ready

    // ---- phase 1: cooperative gather, 8 rounds x 4 samples per warp ----
#pragma unroll 1
    for (int r = 0; r < 8; r++) {
        const int j = wid * 32 + r * 4 + g;
        const float s = (float)j * (1.0f / 255.0f);
        const float z = t_min * (1.0f - s) + t_max * s;
        float c0, c1, c2;
        {
            float p0v = o[0] + d[0] * z, p1v = o[1] + d[1] * z, p2v = o[2] + d[2] * z;
            c0 = (p0v - a0[0]) / (a1[0] - a0[0]) * 2.0f - 1.0f;
            c1 = (p1v - a0[1]) / (a1[1] - a0[1]) * 2.0f - 1.0f;
            c2 = (p2v - a0[2]) / (a1[2] - a0[2]) * 2.0f - 1.0f;
        }
        float sig = 0.0f, r0 = 0.0f, r1 = 0.0f, r2 = 0.0f;
        // MAT_MODE=[(0,1),(0,2),(1,2)], VEC_MODE=[2,1,0]
        gather_plane(0, c0, c1, c2, sub, dxl, q, s_basis, sig, r0, r1, r2);
        gather_plane(1, c0, c2, c1, sub, dxl, q, s_basis, sig, r0, r1, r2);
        gather_plane(2, c1, c2, c0, sub, dxl, q, s_basis, sig, r0, r1, r2);
        // reduce across 8-lane group
#pragma unroll
        for (int off = 1; off < 8; off <<= 1) {
            sig += __shfl_xor_sync(0xffffffffu, sig, off);
            r0  += __shfl_xor_sync(0xffffffffu, r0,  off);
            r1  += __shfl_xor_sync(0xffffffffu, r1,  off);
            r2  += __shfl_xor_sync(0xffffffffu, r2,  off);
        }
        if (sub == 0) {
            s_sig[j] = sig; s_r0[j] = r0; s_r1[j] = r1; s_r2[j] = r2;
        }
    }
    __syncthreads();

    // ---- phase 2: per-sample compositing (thread = sample) ----
    const int j = tid;
    const float s  = (float)j * (1.0f / 255.0f);
    const float z  = t_min * (1.0f - s) + t_max * s;
    const int   ja = (j < 255) ? j : 254;
    const float sA = (float)ja * (1.0f / 255.0f);
    const float sB = (float)(ja + 1) * (1.0f / 255.0f);
    const float dist = (t_min * (1.0f - sB) + t_max * sB)
                     - (t_min * (1.0f - sA) + t_max * sA);
    float cc[3];
#pragma unroll
    for (int k = 0; k < 3; k++) {
        float p = o[k] + d[k] * z;
        cc[k] = (p - a0[k]) / (a1[k] - a0[k]) * 2.0f - 1.0f;
    }
    const bool inside =
        fabsf(cc[0]) <= 1.0f && fabsf(cc[1]) <= 1.0f && fabsf(cc[2]) <= 1.0f;

    const float sig = inside ? s_sig[j] : 0.0f;
    const float r0v = inside ? s_r0[j] : 0.0f;
    const float r1v = inside ? s_r1[j] : 0.0f;
    const float r2v = inside ? s_r2[j] : 0.0f;

    float sp = fmaxf(sig, 0.0f) + log1pf(expf(-fabsf(sig)));
    float alpha = inside ? (1.0f - expf(-sp * dist)) : 0.0f;
    float gg = 1.0f - alpha + 1e-10f;

    // exclusive prefix product across 256 threads
    float p = gg;
#pragma unroll
    for (int off = 1; off < 32; off <<= 1) {
        float n = __shfl_up_sync(0xffffffffu, p, off);
        if (lane >= off) p *= n;
    }
    if (lane == 31) s_warp[wid] = p;
    __syncthreads();
    float woff = 1.0f;
    for (int w = 0; w < wid; w++) woff *= s_warp[w];
    float pexcl = __shfl_up_sync(0xffffffffu, p, 1);
    if (lane == 0) pexcl = 1.0f;
    const float T = woff * pexcl;
    const float weight = alpha * T;

    float cr0 = weight * (1.0f / (1.0f + expf(-r0v)));
    float cr1 = weight * (1.0f / (1.0f + expf(-r1v)));
    float cr2 = weight * (1.0f / (1.0f + expf(-r2v)));
    float czv = weight * z;
    float cw  = weight;

    float vals[5] = {cr0, cr1, cr2, czv, cw};
#pragma unroll
    for (int k = 0; k < 5; k++) {
#pragma unroll
        for (int off = 16; off > 0; off >>= 1)
            vals[k] += __shfl_xor_sync(0xffffffffu, vals[k], off);
    }
    if (lane == 0) {
#pragma unroll
        for (int k = 0; k < 5; k++) s_red[wid][k] = vals[k];
    }
    __syncthreads();
    if (tid == 0) {
        float sum[5] = {0, 0, 0, 0, 0};
#pragma unroll
        for (int w = 0; w < 8; w++)
#pragma unroll
            for (int k = 0; k < 5; k++) sum[k] += s_red[w][k];
        const float acc = sum[4];
        const float bg  = 1.0f - acc;   // WHITE_BG
        out[ray * 3 + 0] = fminf(fmaxf(sum[0] + bg, 0.0f), 1.0f);
        out[ray * 3 + 1] = fminf(fmaxf(sum[1] + bg, 0.0f), 1.0f);
        out[ray * 3 + 2] = fminf(fmaxf(sum[2] + bg, 0.0f), 1.0f);
        out[N_RAYS * 3 + ray] = sum[3];   // depth
    }
}

// ---------------- launch -----------------------------------------------------

extern "C" void kernel_launch(void* const* d_in, const int* in_sizes, int n_in,
                              void* d_out, int out_size) {
    const float* rays  = (const float*)d_in[0];
    const float* dp    = (const float*)d_in[1];
    const float* dl    = (const float*)d_in[2];
    const float* ap    = (const float*)d_in[3];
    const float* al    = (const float*)d_in[4];
    const float* basis = (const float*)d_in[5];
    const float* aabb  = (const float*)d_in[6];
    (void)in_sizes; (void)n_in; (void)out_size;

    transpose_dplane<<<dim3(8, 256, 3), dim3(32, 16)>>>(dp);
    transpose_aplane<<<dim3(8, 256, 3), dim3(32, 24)>>>(ap);
    transpose_lines<<<96, 256>>>(dl, al);
    render_kernel<<<N_RAYS, NS>>>(rays, basis, aabb, (float*)d_out);
}

// round 4
// speedup vs baseline: 1.8454x; 1.1527x over previous
#include <cuda_runtime.h>
#include <cuda_fp16.h>
#include <math.h>

// ----------------------------------------------------------------------------
// OctreeRender (TensoRF tri-plane renderer) — fp16 everything, shuffle-free
// gather, half2 math, pre-paired line tables.
// Output: float[4096*3] rgb_map then float[4096] depth_map
// ----------------------------------------------------------------------------

#define N_RAYS    4096
#define RES       256
#define NS        256
#define DC        16
#define ACP       32    // app channels padded 24 -> 32

// fp16 channel-last scratch (zero-init; pad channels never written => 0)
__device__ __half g_dph[3 * RES * RES * DC];        // [i][y][x][16]
__device__ __half g_aph[3 * RES * RES * ACP];       // [i][y][x][32]
__device__ __half g_dlph[3 * RES * 2 * DC];         // [i][p][pos(2)][16] pairs {L[p],L[p+1]}
__device__ __half g_alph[3 * RES * 2 * ACP];        // [i][p][pos(2)][32] pairs

// ---------------- transpose / pack kernels -----------------------------------

__global__ void transpose_dplane(const float* __restrict__ src) {
    // grid (8,256,3) block (32,16): [i][c][y][x] -> half [i][y][x][16]
    __shared__ float tile[DC][33];
    const int x = blockIdx.x * 32 + threadIdx.x;
    const int y = blockIdx.y;
    const int i = blockIdx.z;
    tile[threadIdx.y][threadIdx.x] =
        __ldg(&src[(((i * DC + threadIdx.y) * RES) + y) * RES + x]);
    __syncthreads();
    const int t = threadIdx.y * 32 + threadIdx.x;   // 0..511
    if (t < 256) {
        const int pos = t >> 3;
        const int hp  = t & 7;
        __half2 v = __floats2half2_rn(tile[hp * 2][pos], tile[hp * 2 + 1][pos]);
        ((__half2*)g_dph)[(((i * RES + y) * RES) + blockIdx.x * 32 + pos) * 8 + hp] = v;
    }
}

__global__ void transpose_aplane(const float* __restrict__ src) {
    // grid (8,256,3) block (32,24): [i][c][y][x] -> half [i][y][x][32]
    __shared__ float tile[24][33];
    const int x = blockIdx.x * 32 + threadIdx.x;
    const int y = blockIdx.y;
    const int i = blockIdx.z;
    tile[threadIdx.y][threadIdx.x] =
        __ldg(&src[(((i * 24 + threadIdx.y) * RES) + y) * RES + x]);
    __syncthreads();
    const int t = threadIdx.y * 32 + threadIdx.x;   // 0..767
    if (t < 384) {
        const int pos = t / 12;
        const int hp  = t - pos * 12;
        __half2 v = __floats2half2_rn(tile[hp * 2][pos], tile[hp * 2 + 1][pos]);
        ((__half2*)g_aph)[(((i * RES + y) * RES) + blockIdx.x * 32 + pos) * 16 + hp] = v;
    }
}

__global__ void pack_lines(const float* __restrict__ dl,
                           const float* __restrict__ al) {
    const int tid = blockIdx.x * blockDim.x + threadIdx.x;
    // density pairs: bits [c:4][pos:1][p:8][i:2]  (3*256*2*16 = 24576)
    if (tid < 3 * RES * 2 * DC) {
        const int c   = tid & 15;
        const int pos = (tid >> 4) & 1;
        const int p   = (tid >> 5) & 255;
        const int i   = tid >> 13;
        const int pp  = (p + pos < 255) ? (p + pos) : 255;
        g_dlph[tid] = __float2half(__ldg(&dl[(i * DC + c) * RES + pp]));
    }
    // app pairs: bits [c:5][pos:1][p:8][i:2]  (3*256*2*32 = 49152)
    if (tid < 3 * RES * 2 * ACP) {
        const int c   = tid & 31;
        const int pos = (tid >> 5) & 1;
        const int p   = (tid >> 6) & 255;
        const int i   = tid >> 14;
        const int pp  = (p + pos < 255) ? (p + pos) : 255;
        float v = (c < 24) ? __ldg(&al[(i * 24 + c) * RES + pp]) : 0.0f;
        g_alph[tid] = __float2half(v);
    }
}

// ---------------- render -----------------------------------------------------

__device__ __forceinline__ void grid_coord(float u, float& w, int& i0) {
    float f  = (u + 1.0f) * 0.5f * 255.0f;
    float f0 = fminf(fmaxf(floorf(f), 0.0f), 254.0f);
    i0 = (int)f0;
    w  = f - f0;
}

// one plane, cooperative across 8 lanes
__device__ __forceinline__ void gather_plane(
    int i, int x0, float wx, int y0, float wy, int p0, float wl,
    int oct, int xl, int yl, int xa, int qa,
    const __half2* __restrict__ s_bh2,
    float& sig, __half2& r0h, __half2& r1h, __half2& r2h)
{
    const uint4* __restrict__ dpu4 = reinterpret_cast<const uint4*>(g_dph);
    const uint4* __restrict__ dlu4 = reinterpret_cast<const uint4*>(g_dlph);
    const uint4* __restrict__ apu4 = reinterpret_cast<const uint4*>(g_aph);
    const uint4* __restrict__ alu4 = reinterpret_cast<const uint4*>(g_alph);

    const __half2 wl2  = __float2half2_rn(wl);
    const __half2 iwl2 = __float2half2_rn(1.0f - wl);

    // ---- density: corner-weight formulation, no shuffles ----
    {
        const float fx = xl ? wx : (1.0f - wx);
        const float fy = yl ? wy : (1.0f - wy);
        const float cw = fx * fy;
        uint4 V  = dpu4[((i * RES + y0 + yl) * RES + x0 + xl) * 2 + oct];
        uint4 L0 = dlu4[(i * RES + p0) * 4 + oct];
        uint4 L1 = dlu4[(i * RES + p0) * 4 + 2 + oct];
        const __half2* Vh  = reinterpret_cast<const __half2*>(&V);
        const __half2* L0h = reinterpret_cast<const __half2*>(&L0);
        const __half2* L1h = reinterpret_cast<const __half2*>(&L1);
        __half2 acc = __float2half2_rn(0.0f);
#pragma unroll
        for (int hp = 0; hp < 4; hp++) {
            __half2 lint = __hfma2(L1h[hp], wl2, __hmul2(L0h[hp], iwl2));
            acc = __hfma2(Vh[hp], lint, acc);
        }
        float2 af = __half22float2(acc);
        sig += cw * (af.x + af.y);
    }

    // ---- app: lane holds oct qa of column x0+xa, both y rows ----
    {
        const float fxa = xa ? wx : (1.0f - wx);
        const __half2 fxa2 = __float2half2_rn(fxa);
        const __half2 wy2  = __float2half2_rn(wy);
        const __half2 iwy2 = __float2half2_rn(1.0f - wy);
        uint4 A  = apu4[((i * RES + y0) * RES + x0 + xa) * 4 + qa];
        uint4 B  = apu4[((i * RES + y0 + 1) * RES + x0 + xa) * 4 + qa];
        uint4 L0 = alu4[(i * RES + p0) * 8 + qa];
        uint4 L1 = alu4[(i * RES + p0) * 8 + 4 + qa];
        const __half2* Ah  = reinterpret_cast<const __half2*>(&A);
        const __half2* Bh  = reinterpret_cast<const __half2*>(&B);
        const __half2* L0h = reinterpret_cast<const __half2*>(&L0);
        const __half2* L1h = reinterpret_cast<const __half2*>(&L1);
        const int bb = i * 16 + qa * 4;
#pragma unroll
        for (int hp = 0; hp < 4; hp++) {
            __half2 m = __hmul2(__hfma2(Bh[hp], wy2, __hmul2(Ah[hp], iwy2)), fxa2);
            __half2 l = __hfma2(L1h[hp], wl2, __hmul2(L0h[hp], iwl2));
            __half2 f = __hmul2(m, l);
            r0h = __hfma2(f, s_bh2[bb + hp], r0h);
            r1h = __hfma2(f, s_bh2[48 + bb + hp], r1h);
            r2h = __hfma2(f, s_bh2[96 + bb + hp], r2h);
        }
    }
}

__global__ __launch_bounds__(NS, 3) void render_kernel(
    const float* __restrict__ rays,
    const float* __restrict__ basis,
    const float* __restrict__ aabb,
    float* __restrict__ out) {
    __shared__ __half2 s_bh2[144];      // [k(3)][i(3)][q(4)][hp(4)]
    __shared__ float s_sig[NS];
    __shared__ float s_r0[NS], s_r1[NS], s_r2[NS];
    __shared__ float s_warp[8];
    __shared__ float s_red[8][5];

    const int ray  = blockIdx.x;
    const int tid  = threadIdx.x;
    const int lane = tid & 31;
    const int wid  = tid >> 5;
    const int g    = lane >> 3;
    const int sub  = lane & 7;
    const int oct  = sub & 1;          // density channel octet
    const int xl   = (sub >> 1) & 1;   // density corner x
    const int yl   = sub >> 2;         // density corner y
    const int xa   = sub >> 2;         // app column x
    const int qa   = sub & 3;          // app channel octet

    // basis -> half2, padded to 32 channels per plane
    if (tid < 144) {
        const int k  = tid / 48;
        const int rm = tid - k * 48;
        const int i  = rm >> 4;
        const int r2 = rm & 15;
        const int q  = r2 >> 2;
        const int hp = r2 & 3;
        const int c0 = q * 8 + hp * 2;
        float b0 = (c0 < 24)     ? __ldg(&basis[(i * 24 + c0) * 3 + k])     : 0.0f;
        float b1 = (c0 + 1 < 24) ? __ldg(&basis[(i * 24 + c0 + 1) * 3 + k]) : 0.0f;
        s_bh2[tid] = __floats2half2_rn(b0, b1);
    }

    float o[3], d[3], a0[3], a1[3];
#pragma unroll
    for (int k = 0; k < 3; k++) {
        o[k]  = __ldg(&rays[ray * 6 + k]);
        d[k]  = __ldg(&rays[ray * 6 + 3 + k]);
        a0[k] = __ldg(&aabb[k]);
        a1[k] = __ldg(&aabb[3 + k]);
    }
    float t_min = -1e30f, t_max = 1e30f;
#pragma unroll
    for (int k = 0; k < 3; k++) {
        float vk = (fabsf(d[k]) < 1e-6f) ? 1e-6f : d[k];
        float ra = (a1[k] - o[k]) / vk;
        float rb = (a0[k] - o[k]) / vk;
        t_min = fmaxf(t_min, fminf(ra, rb));
        t_max = fminf(t_max, fmaxf(ra, rb));
    }
    t_min = fmaxf(t_min, 0.05f);
    t_max = fmaxf(t_max, t_min + 0.001f);

    __syncthreads();

    // ---- phase 1: cooperative gather ----
#pragma unroll 1
    for (int r = 0; r < 8; r++) {
        const int j = wid * 32 + r * 4 + g;
        const float s = (float)j * (1.0f / 255.0f);
        const float z = t_min * (1.0f - s) + t_max * s;
        float c0, c1, c2;
        c0 = (o[0] + d[0] * z - a0[0]) / (a1[0] - a0[0]) * 2.0f - 1.0f;
        c1 = (o[1] + d[1] * z - a0[1]) / (a1[1] - a0[1]) * 2.0f - 1.0f;
        c2 = (o[2] + d[2] * z - a0[2]) / (a1[2] - a0[2]) * 2.0f - 1.0f;
        int xi0, xi1, xi2; float w0, w1, w2;
        grid_coord(c0, w0, xi0);
        grid_coord(c1, w1, xi1);
        grid_coord(c2, w2, xi2);

        float sig = 0.0f;
        __half2 r0h = __float2half2_rn(0.0f);
        __half2 r1h = r0h, r2h = r0h;
        // MAT_MODE=[(0,1),(0,2),(1,2)], VEC_MODE=[2,1,0]
        gather_plane(0, xi0, w0, xi1, w1, xi2, w2, oct, xl, yl, xa, qa, s_bh2, sig, r0h, r1h, r2h);
        gather_plane(1, xi0, w0, xi2, w2, xi1, w1, oct, xl, yl, xa, qa, s_bh2, sig, r0h, r1h, r2h);
        gather_plane(2, xi1, w1, xi2, w2, xi0, w0, oct, xl, yl, xa, qa, s_bh2, sig, r0h, r1h, r2h);

        float2 f0 = __half22float2(r0h);
        float2 f1 = __half22float2(r1h);
        float2 f2 = __half22float2(r2h);
        float r0 = f0.x + f0.y, r1 = f1.x + f1.y, r2 = f2.x + f2.y;
#pragma unroll
        for (int off = 1; off < 8; off <<= 1) {
            sig += __shfl_xor_sync(0xffffffffu, sig, off);
            r0  += __shfl_xor_sync(0xffffffffu, r0,  off);
            r1  += __shfl_xor_sync(0xffffffffu, r1,  off);
            r2  += __shfl_xor_sync(0xffffffffu, r2,  off);
        }
        if (sub == 0) {
            s_sig[j] = sig; s_r0[j] = r0; s_r1[j] = r1; s_r2[j] = r2;
        }
    }
    __syncthreads();

    // ---- phase 2: compositing (thread = sample) ----
    const int j = tid;
    const float s  = (float)j * (1.0f / 255.0f);
    const float z  = t_min * (1.0f - s) + t_max * s;
    const int   ja = (j < 255) ? j : 254;
    const float sA = (float)ja * (1.0f / 255.0f);
    const float sB = (float)(ja + 1) * (1.0f / 255.0f);
    const float dist = (t_min * (1.0f - sB) + t_max * sB)
                     - (t_min * (1.0f - sA) + t_max * sA);
    float cc[3];
#pragma unroll
    for (int k = 0; k < 3; k++) {
        float p = o[k] + d[k] * z;
        cc[k] = (p - a0[k]) / (a1[k] - a0[k]) * 2.0f - 1.0f;
    }
    const bool inside =
        fabsf(cc[0]) <= 1.0f && fabsf(cc[1]) <= 1.0f && fabsf(cc[2]) <= 1.0f;

    const float sig = inside ? s_sig[j] : 0.0f;
    const float r0v = inside ? s_r0[j] : 0.0f;
    const float r1v = inside ? s_r1[j] : 0.0f;
    const float r2v = inside ? s_r2[j] : 0.0f;

    float sp = fmaxf(sig, 0.0f) + log1pf(expf(-fabsf(sig)));
    float alpha = inside ? (1.0f - expf(-sp * dist)) : 0.0f;
    float gg = 1.0f - alpha + 1e-10f;

    float p = gg;
#pragma unroll
    for (int off = 1; off < 32; off <<= 1) {
        float n = __shfl_up_sync(0xffffffffu, p, off);
        if (lane >= off) p *= n;
    }
    if (lane == 31) s_warp[wid] = p;
    __syncthreads();
    float woff = 1.0f;
    for (int w = 0; w < wid; w++) woff *= s_warp[w];
    float pexcl = __shfl_up_sync(0xffffffffu, p, 1);
    if (lane == 0) pexcl = 1.0f;
    const float T = woff * pexcl;
    const float weight = alpha * T;

    float cr0 = weight * (1.0f / (1.0f + expf(-r0v)));
    float cr1 = weight * (1.0f / (1.0f + expf(-r1v)));
    float cr2 = weight * (1.0f / (1.0f + expf(-r2v)));
    float czv = weight * z;
    float cw  = weight;

    float vals[5] = {cr0, cr1, cr2, czv, cw};
#pragma unroll
    for (int k = 0; k < 5; k++) {
#pragma unroll
        for (int off = 16; off > 0; off >>= 1)
            vals[k] += __shfl_xor_sync(0xffffffffu, vals[k], off);
    }
    if (lane == 0) {
#pragma unroll
        for (int k = 0; k < 5; k++) s_red[wid][k] = vals[k];
    }
    __syncthreads();
    if (tid == 0) {
        float sum[5] = {0, 0, 0, 0, 0};
#pragma unroll
        for (int w = 0; w < 8; w++)
#pragma unroll
            for (int k = 0; k < 5; k++) sum[k] += s_red[w][k];
        const float acc = sum[4];
        const float bg  = 1.0f - acc;   // WHITE_BG
        out[ray * 3 + 0] = fminf(fmaxf(sum[0] + bg, 0.0f), 1.0f);
        out[ray * 3 + 1] = fminf(fmaxf(sum[1] + bg, 0.0f), 1.0f);
        out[ray * 3 + 2] = fminf(fmaxf(sum[2] + bg, 0.0f), 1.0f);
        out[N_RAYS * 3 + ray] = sum[3];
    }
}

// ---------------- launch -----------------------------------------------------

extern "C" void kernel_launch(void* const* d_in, const int* in_sizes, int n_in,
                              void* d_out, int out_size) {
    const float* rays  = (const float*)d_in[0];
    const float* dp    = (const float*)d_in[1];
    const float* dl    = (const float*)d_in[2];
    const float* ap    = (const float*)d_in[3];
    const float* al    = (const float*)d_in[4];
    const float* basis = (const float*)d_in[5];
    const float* aabb  = (const float*)d_in[6];
    (void)in_sizes; (void)n_in; (void)out_size;

    transpose_dplane<<<dim3(8, 256, 3), dim3(32, 16)>>>(dp);
    transpose_aplane<<<dim3(8, 256, 3), dim3(32, 24)>>>(ap);
    pack_lines<<<192, 256>>>(dl, al);
    render_kernel<<<N_RAYS, NS>>>(rays, basis, aabb, (float*)d_out);
}